// round 6
// baseline (speedup 1.0000x reference)
#include <cuda_runtime.h>
#include <cuda_fp16.h>
#include <stdint.h>

#define NUM_EXPERTS 8
#define BATCH 4096
#define DM 1024
#define VOCAB 32000

#define TM 128                  // rows per chunk = BM
#define BN 256
#define BK 32
#define NKI (DM / BK)           // 32 k-iterations
#define MAXC 40                 // max chunks: 4096/128 + 8 pad
#define XSROWS (MAXC * TM)      // 5120 padded rows

// XOR swizzle on the 8-byte slot index (proven 2-phase for STS and LDS)
#define SWZ(m) ((((m) & 3)) ^ ((((m) >> 2) & 3)))

// ---------------- device scratch (no allocations allowed) ----------------
__device__ int g_rows[BATCH];
__device__ int g_offsets[NUM_EXPERTS + 1];
__device__ int g_chunk_e[MAXC];
__device__ int g_chunk_pm0[MAXC];
__device__ int g_nchunks;
__device__ int g_prow[XSROWS];
__device__ __half g_xsh[(size_t)XSROWS * DM];   // fp16 gathered x (10.5 MB)

// ---------------------------------------------------------------------------
// Kernel 1: group rows by expert (ptr % 8), build padded 128-row chunk table.
// Pointer dtype auto-detect (JAX x64-off downcasts int64->int32), as in R3.
// ---------------------------------------------------------------------------
__global__ void group_rows_kernel(const uint32_t* __restrict__ ptr_words) {
    __shared__ int counts[NUM_EXPERTS];
    __shared__ int cursor[NUM_EXPERTS];
    __shared__ int pad_off[NUM_EXPERTS];
    __shared__ int odd_nonzero;
    const int tid = threadIdx.x;

    if (tid == 0) odd_nonzero = 0;
    if (tid < NUM_EXPERTS) counts[tid] = 0;
    __syncthreads();

    int local_nz = 0;
    for (int i = tid; i < BATCH / 2; i += blockDim.x)
        if (ptr_words[2 * i + 1] != 0u) local_nz = 1;
    if (local_nz) atomicOr(&odd_nonzero, 1);
    __syncthreads();
    const bool is_i64 = (odd_nonzero == 0);

    for (int i = tid; i < BATCH; i += blockDim.x) {
        uint32_t v = is_i64 ? ptr_words[2 * i] : ptr_words[i];
        atomicAdd(&counts[v & (NUM_EXPERTS - 1)], 1);
    }
    __syncthreads();
    if (tid == 0) {
        int acc = 0, nc = 0, pbase = 0;
        for (int e = 0; e < NUM_EXPERTS; e++) {
            g_offsets[e] = acc;
            cursor[e] = acc;
            pad_off[e] = pbase;
            int cnt = counts[e];
            int nch = (cnt + TM - 1) / TM;
            for (int j = 0; j < nch; j++) {
                g_chunk_e[nc] = e;
                g_chunk_pm0[nc] = pbase + j * TM;
                nc++;
            }
            pbase += nch * TM;
            acc += cnt;
        }
        g_offsets[NUM_EXPERTS] = acc;
        g_nchunks = nc;
    }
    __syncthreads();
    for (int i = tid; i < XSROWS; i += blockDim.x) g_prow[i] = -1;
    for (int i = tid; i < BATCH; i += blockDim.x) {
        uint32_t v = is_i64 ? ptr_words[2 * i] : ptr_words[i];
        int pos = atomicAdd(&cursor[v & (NUM_EXPERTS - 1)], 1);
        g_rows[pos] = i;
    }
    __syncthreads();
    for (int i = tid; i < BATCH; i += blockDim.x) {
        int e = 0;
        while (!(i >= g_offsets[e] && i < g_offsets[e + 1])) e++;
        g_prow[pad_off[e] + (i - g_offsets[e])] = g_rows[i];
    }
}

// ---------------------------------------------------------------------------
// Kernel 2: gather + RN-round x rows to fp16 into padded buffer (zeros pad).
// ---------------------------------------------------------------------------
__global__ void pack_kernel(const float* __restrict__ x) {
    const int p = blockIdx.x;
    const int r = g_prow[p];
    __half2* dst = reinterpret_cast<__half2*>(g_xsh + (size_t)p * DM);
    if (r >= 0) {
        const float2* src = reinterpret_cast<const float2*>(x + (size_t)r * DM);
        for (int i = threadIdx.x; i < DM / 2; i += blockDim.x)
            dst[i] = __float22half2_rn(src[i]);
    } else {
        for (int i = threadIdx.x; i < DM / 2; i += blockDim.x)
            dst[i] = __float2half2_rn(0.f);
    }
}

// ---------------------------------------------------------------------------
// Kernel 3: fp16 mma.sync GEMM, f32 accumulate.
// CTA = 128 rows x 256 vocab cols. 8 warps (2m x 4n), warp tile 64x64.
// BK=32 (two k16 slices), 2-stage smem double buffer, register staging.
// Smem word w[c'] = halves (2c', 2c'+1); stored as (w[c], w[c+4]) 8-byte
// pairs at slot q with content rule c = q ^ SWZ(row), giving 2-phase
// (minimum) access for both STS and fragment LDS.64.
// ---------------------------------------------------------------------------
__device__ __forceinline__ void mma_f16(float& d0, float& d1, float& d2, float& d3,
                                        uint32_t a0, uint32_t a1, uint32_t a2, uint32_t a3,
                                        uint32_t b0, uint32_t b1) {
    asm volatile(
        "mma.sync.aligned.m16n8k16.row.col.f32.f16.f16.f32 "
        "{%0,%1,%2,%3}, {%4,%5,%6,%7}, {%8,%9}, {%0,%1,%2,%3};"
        : "+f"(d0), "+f"(d1), "+f"(d2), "+f"(d3)
        : "r"(a0), "r"(a1), "r"(a2), "r"(a3), "r"(b0), "r"(b1));
}

// smem u32 layout: srow[128] | A[2][2][128][8] | B[2][2][256][8]
#define SM_A_OFF 128
#define SM_B_OFF (SM_A_OFF + 2 * 2 * TM * 8)
#define SMEM_U32 (SM_B_OFF + 2 * 2 * BN * 8)
#define SMEM_TOTAL (SMEM_U32 * 4)      // 49664 B

__global__ void __launch_bounds__(256, 1)
tc_gemm_kernel(const float* __restrict__ W,
               const float* __restrict__ bias,
               float* __restrict__ out) {
    const int cx = blockIdx.x;
    if (cx >= g_nchunks) return;
    const int e = g_chunk_e[cx];
    const int pm0 = g_chunk_pm0[cx];
    const int n0 = blockIdx.y * BN;

    extern __shared__ uint32_t smu[];
    int* srow = reinterpret_cast<int*>(smu);
    uint32_t* As = smu + SM_A_OFF;
    uint32_t* Bs = smu + SM_B_OFF;

    const int tid = threadIdx.x;
    const int w = tid >> 5, lane = tid & 31;
    const int wm = (w & 1) * 64, wn = (w >> 1) * 64;
    const int grp = lane >> 2, c = lane & 3;

    if (tid < TM) srow[tid] = g_prow[pm0 + tid];

    const float* gW = W + (size_t)e * VOCAB * DM;

    float acc[4][8][4];
    #pragma unroll
    for (int mt = 0; mt < 4; mt++)
        #pragma unroll
        for (int nt = 0; nt < 8; nt++)
            #pragma unroll
            for (int q = 0; q < 4; q++) acc[mt][nt][q] = 0.f;

    // staging: A one 32-byte unit (already fp16), B eight float4 (raw fp32)
    const int am = tid >> 1, asl = tid & 1;     // A: row, k16-slice
    const int bn = tid;                          // B: row (n)
    uint4 a_st[2];
    float4 b_st[8];

    auto load_regs = [&](int kt) {
        const int k0 = kt * BK;
        const __half* ga = g_xsh + (size_t)(pm0 + am) * DM + k0 + asl * 16;
        a_st[0] = reinterpret_cast<const uint4*>(ga)[0];
        a_st[1] = reinterpret_cast<const uint4*>(ga)[1];
        const float4* gb = reinterpret_cast<const float4*>(gW + (size_t)(n0 + bn) * DM + k0);
        #pragma unroll
        for (int j = 0; j < 8; j++) b_st[j] = gb[j];
    };

    auto sts = [&](int st) {
        // A: 8 words (one k16 slice)
        uint32_t wa[8] = {a_st[0].x, a_st[0].y, a_st[0].z, a_st[0].w,
                          a_st[1].x, a_st[1].y, a_st[1].z, a_st[1].w};
        uint32_t* arow = As + (((st * 2 + asl) * TM) + am) * 8;
        #pragma unroll
        for (int i = 0; i < 4; i++) {
            int q = i ^ ((am >> 2) & 3);
            int cc = i ^ (am & 3);             // = q ^ SWZ(am)
            *reinterpret_cast<uint2*>(arow + q * 2) = make_uint2(wa[cc], wa[cc + 4]);
        }
        // B: cvt fp32 -> fp16x2, 16 words (two k16 slices)
        uint32_t wb[16];
        #pragma unroll
        for (int j = 0; j < 8; j++) {
            __half2 h0 = __float22half2_rn(make_float2(b_st[j].x, b_st[j].y));
            __half2 h1 = __float22half2_rn(make_float2(b_st[j].z, b_st[j].w));
            wb[2 * j] = *reinterpret_cast<uint32_t*>(&h0);
            wb[2 * j + 1] = *reinterpret_cast<uint32_t*>(&h1);
        }
        #pragma unroll
        for (int s = 0; s < 2; s++) {
            uint32_t* brow = Bs + (((st * 2 + s) * BN) + bn) * 8;
            #pragma unroll
            for (int i = 0; i < 4; i++) {
                int q = i ^ ((bn >> 2) & 3);
                int cc = i ^ (bn & 3);
                *reinterpret_cast<uint2*>(brow + q * 2) = make_uint2(wb[s * 8 + cc], wb[s * 8 + cc + 4]);
            }
        }
    };

    auto compute = [&](int st) {
        #pragma unroll
        for (int s = 0; s < 2; s++) {
            const uint32_t* Abase = As + (st * 2 + s) * TM * 8;
            const uint32_t* Bbase = Bs + (st * 2 + s) * BN * 8;
            uint2 af0[4], af1[4];
            #pragma unroll
            for (int mt = 0; mt < 4; mt++) {
                int r = wm + mt * 16 + grp;
                af0[mt] = *reinterpret_cast<const uint2*>(Abase + r * 8 + ((c ^ SWZ(r)) << 1));
                int r8 = r + 8;
                af1[mt] = *reinterpret_cast<const uint2*>(Abase + r8 * 8 + ((c ^ SWZ(r8)) << 1));
            }
            uint2 bf[8];
            #pragma unroll
            for (int nt = 0; nt < 8; nt++) {
                int n = wn + nt * 8 + grp;
                bf[nt] = *reinterpret_cast<const uint2*>(Bbase + n * 8 + ((c ^ SWZ(n)) << 1));
            }
            #pragma unroll
            for (int mt = 0; mt < 4; mt++)
                #pragma unroll
                for (int nt = 0; nt < 8; nt++)
                    mma_f16(acc[mt][nt][0], acc[mt][nt][1], acc[mt][nt][2], acc[mt][nt][3],
                            af0[mt].x, af1[mt].x, af0[mt].y, af1[mt].y,
                            bf[nt].x, bf[nt].y);
        }
    };

    load_regs(0);
    sts(0);
    __syncthreads();

    for (int kt = 0; kt < NKI; kt++) {
        const int st = kt & 1;
        if (kt + 1 < NKI) load_regs(kt + 1);
        compute(st);
        if (kt + 1 < NKI) {
            sts(1 - st);
            __syncthreads();
        }
    }

    // ---- epilogue: bias + scatter float2 stores ----
    const float* bp = bias + (size_t)e * VOCAB + n0 + wn + c * 2;
    float2 bias2[8];
    #pragma unroll
    for (int nt = 0; nt < 8; nt++)
        bias2[nt] = *reinterpret_cast<const float2*>(bp + nt * 8);

    #pragma unroll
    for (int mt = 0; mt < 4; mt++) {
        const int r0 = wm + mt * 16 + grp;
        const int row0 = srow[r0];
        const int row1 = srow[r0 + 8];
        #pragma unroll
        for (int nt = 0; nt < 8; nt++) {
            const int col = n0 + wn + nt * 8 + c * 2;
            if (row0 >= 0) {
                float2 o = make_float2(acc[mt][nt][0] + bias2[nt].x,
                                       acc[mt][nt][1] + bias2[nt].y);
                *reinterpret_cast<float2*>(out + (size_t)row0 * VOCAB + col) = o;
            }
            if (row1 >= 0) {
                float2 o = make_float2(acc[mt][nt][2] + bias2[nt].x,
                                       acc[mt][nt][3] + bias2[nt].y);
                *reinterpret_cast<float2*>(out + (size_t)row1 * VOCAB + col) = o;
            }
        }
    }
}

// ---------------------------------------------------------------------------
// Host launch
// ---------------------------------------------------------------------------
extern "C" void kernel_launch(void* const* d_in, const int* in_sizes, int n_in,
                              void* d_out, int out_size) {
    const float*    x    = (const float*)d_in[0];
    const uint32_t* ptr  = (const uint32_t*)d_in[1];
    const float*    W    = (const float*)d_in[2];
    const float*    bias = (const float*)d_in[3];
    float*          out  = (float*)d_out;

    static bool attr_done = false;
    if (!attr_done) {
        cudaFuncSetAttribute(tc_gemm_kernel,
                             cudaFuncAttributeMaxDynamicSharedMemorySize, SMEM_TOTAL);
        attr_done = true;
    }

    group_rows_kernel<<<1, 1024>>>(ptr);
    pack_kernel<<<XSROWS, 128>>>(x);

    dim3 grid(MAXC, VOCAB / BN);   // chunk-fastest -> L2 absorbs W reuse
    tc_gemm_kernel<<<grid, 256, SMEM_TOTAL>>>(W, bias, out);
}

// round 7
// speedup vs baseline: 1.1787x; 1.1787x over previous
#include <cuda_runtime.h>
#include <stdint.h>

#define NUM_EXPERTS 8
#define BATCH 4096
#define DM 1024
#define VOCAB 32000

#define TM 128                  // rows per chunk = BM
#define BN 256
#define BK 32
#define NKI (DM / BK)           // 32 k-iterations
#define NTILES (VOCAB / BN)     // 125
#define MAXC 40                 // max chunks: 4096/128 + 8 pad
#define XSROWS (MAXC * TM)      // 5120 padded rows

// ---------------- device scratch (no allocations allowed) ----------------
__device__ int g_rows[BATCH];
__device__ int g_offsets[NUM_EXPERTS + 1];
__device__ int g_chunk_e[MAXC];
__device__ int g_chunk_pm0[MAXC];
__device__ int g_nchunks;
__device__ int g_work;                       // dynamic work counter
__device__ int g_prow[XSROWS];
__device__ float g_xs[(size_t)XSROWS * DM];  // tf32-rounded gathered x

// ---------------------------------------------------------------------------
// Kernel 1: group rows by expert (ptr % 8), build padded 128-row chunk table.
// Pointer dtype auto-detect (JAX x64-off downcasts int64->int32), as in R3.
// Also resets the persistent-GEMM work counter (every replay).
// ---------------------------------------------------------------------------
__global__ void group_rows_kernel(const uint32_t* __restrict__ ptr_words) {
    __shared__ int counts[NUM_EXPERTS];
    __shared__ int cursor[NUM_EXPERTS];
    __shared__ int pad_off[NUM_EXPERTS];
    __shared__ int odd_nonzero;
    const int tid = threadIdx.x;

    if (tid == 0) { odd_nonzero = 0; g_work = 0; }
    if (tid < NUM_EXPERTS) counts[tid] = 0;
    __syncthreads();

    int local_nz = 0;
    for (int i = tid; i < BATCH / 2; i += blockDim.x)
        if (ptr_words[2 * i + 1] != 0u) local_nz = 1;
    if (local_nz) atomicOr(&odd_nonzero, 1);
    __syncthreads();
    const bool is_i64 = (odd_nonzero == 0);

    for (int i = tid; i < BATCH; i += blockDim.x) {
        uint32_t v = is_i64 ? ptr_words[2 * i] : ptr_words[i];
        atomicAdd(&counts[v & (NUM_EXPERTS - 1)], 1);
    }
    __syncthreads();
    if (tid == 0) {
        int acc = 0, nc = 0, pbase = 0;
        for (int e = 0; e < NUM_EXPERTS; e++) {
            g_offsets[e] = acc;
            cursor[e] = acc;
            pad_off[e] = pbase;
            int cnt = counts[e];
            int nch = (cnt + TM - 1) / TM;
            for (int j = 0; j < nch; j++) {
                g_chunk_e[nc] = e;
                g_chunk_pm0[nc] = pbase + j * TM;
                nc++;
            }
            pbase += nch * TM;
            acc += cnt;
        }
        g_offsets[NUM_EXPERTS] = acc;
        g_nchunks = nc;
    }
    __syncthreads();
    for (int i = tid; i < XSROWS; i += blockDim.x) g_prow[i] = -1;
    for (int i = tid; i < BATCH; i += blockDim.x) {
        uint32_t v = is_i64 ? ptr_words[2 * i] : ptr_words[i];
        int pos = atomicAdd(&cursor[v & (NUM_EXPERTS - 1)], 1);
        g_rows[pos] = i;
    }
    __syncthreads();
    for (int i = tid; i < BATCH; i += blockDim.x) {
        int e = 0;
        while (!(i >= g_offsets[e] && i < g_offsets[e + 1])) e++;
        g_prow[pad_off[e] + (i - g_offsets[e])] = g_rows[i];
    }
}

// ---------------------------------------------------------------------------
// Kernel 2: gather + RN-round x rows to tf32 into padded buffer (zeros pad).
// ---------------------------------------------------------------------------
__device__ __forceinline__ float to_tf32_rn(float v) {
    uint32_t b;
    asm("cvt.rna.tf32.f32 %0, %1;" : "=r"(b) : "f"(v));
    return __uint_as_float(b);
}
__device__ __forceinline__ uint32_t cvt_tf32_bits(float v) {
    uint32_t b;
    asm("cvt.rna.tf32.f32 %0, %1;" : "=r"(b) : "f"(v));
    return b;
}

__global__ void pack_kernel(const float* __restrict__ x) {
    const int p = blockIdx.x;
    const int r = g_prow[p];
    float4* dst = reinterpret_cast<float4*>(g_xs + (size_t)p * DM);
    if (r >= 0) {
        const float4* src = reinterpret_cast<const float4*>(x + (size_t)r * DM);
        for (int i = threadIdx.x; i < DM / 4; i += blockDim.x) {
            float4 v = src[i];
            v.x = to_tf32_rn(v.x); v.y = to_tf32_rn(v.y);
            v.z = to_tf32_rn(v.z); v.w = to_tf32_rn(v.w);
            dst[i] = v;
        }
    } else {
        float4 z = make_float4(0.f, 0.f, 0.f, 0.f);
        for (int i = threadIdx.x; i < DM / 4; i += blockDim.x) dst[i] = z;
    }
}

// ---------------------------------------------------------------------------
// Kernel 3: persistent tf32 mma.sync GEMM (compute identical to R5 kernel).
// Grid = #SMs, 1 CTA/SM. Dynamic work ids; next item's id prefetched during
// the current item so its gmem loads issue before the epilogue (latency
// hidden behind epilogue stores). srow double-buffered per item parity.
// ---------------------------------------------------------------------------
__device__ __forceinline__ void mma_tf32(float& d0, float& d1, float& d2, float& d3,
                                         uint32_t a0, uint32_t a1, uint32_t a2, uint32_t a3,
                                         uint32_t b0, uint32_t b1) {
    asm volatile(
        "mma.sync.aligned.m16n8k8.row.col.f32.tf32.tf32.f32 "
        "{%0,%1,%2,%3}, {%4,%5,%6,%7}, {%8,%9}, {%0,%1,%2,%3};"
        : "+f"(d0), "+f"(d1), "+f"(d2), "+f"(d3)
        : "r"(a0), "r"(a1), "r"(a2), "r"(a3), "r"(b0), "r"(b1));
}

// smem floats: meta[16] | srow[2][128] | As[2][4][TM][8] | Bs[2][4][BN][8]
#define SM_SROW 16
#define SM_AOFF (SM_SROW + 2 * TM)
#define SM_BOFF (SM_AOFF + 2 * 4 * TM * 8)
#define SMEM_F  (SM_BOFF + 2 * 4 * BN * 8)
#define SMEM_TOTAL (SMEM_F * 4)   // 99,392 B -> 1 CTA/SM

__global__ void __launch_bounds__(256, 1)
tc_gemm_kernel(const float* __restrict__ W,
               const float* __restrict__ bias,
               float* __restrict__ out) {
    extern __shared__ float sm[];
    volatile int* s_nid = reinterpret_cast<volatile int*>(sm);
    int* srow = reinterpret_cast<int*>(sm + SM_SROW);   // [2][TM]
    float* As = sm + SM_AOFF;
    float* Bs = sm + SM_BOFF;

    const int tid = threadIdx.x;
    const int w = tid >> 5, lane = tid & 31;
    const int wm = (w & 1) * 64, wn = (w >> 1) * 64;
    const int grp = lane >> 2, c = lane & 3;

    const int nchunks = g_nchunks;
    const int n_items = nchunks * NTILES;

    // ---- current/next item state ----
    int cur_e, cur_pm0, cur_n0;
    int nxt_e = 0, nxt_pm0 = 0, nxt_n0 = 0;
    bool nxt_valid = false;
    int par = 0;

    float acc[4][8][4];
    #pragma unroll
    for (int mt = 0; mt < 4; mt++)
        #pragma unroll
        for (int nt = 0; nt < 8; nt++)
            #pragma unroll
            for (int q = 0; q < 4; q++) acc[mt][nt][q] = 0.f;

    float4 pa[2][2];
    float4 pb[4][2];

    auto load_regs = [&](int e, int pm0, int n0, int kt) {
        const int k0 = kt * BK;
        const float* gWe = W + (size_t)e * VOCAB * DM;
        #pragma unroll
        for (int i = 0; i < 2; i++) {
            int u = tid + 256 * i;
            int m = u >> 2, j = u & 3;
            const float* ga = g_xs + (size_t)(pm0 + m) * DM + k0 + j * 8;
            pa[i][0] = *reinterpret_cast<const float4*>(ga);
            pa[i][1] = *reinterpret_cast<const float4*>(ga + 4);
        }
        #pragma unroll
        for (int i = 0; i < 4; i++) {
            int u = tid + 256 * i;
            int n = u >> 2, j = u & 3;
            const float* gb = gWe + (size_t)(n0 + n) * DM + k0 + j * 8;
            pb[i][0] = *reinterpret_cast<const float4*>(gb);
            pb[i][1] = *reinterpret_cast<const float4*>(gb + 4);
        }
    };

    auto sts = [&](int st) {
        #pragma unroll
        for (int i = 0; i < 2; i++) {
            int u = tid + 256 * i;
            int m = u >> 2, j = u & 3;
            float* base = As + (((st * 4 + j) * TM + m) << 3);
            float f0[4] = {pa[i][0].x, pa[i][0].y, pa[i][0].z, pa[i][0].w};
            float f1[4] = {pa[i][1].x, pa[i][1].y, pa[i][1].z, pa[i][1].w};
            #pragma unroll
            for (int cc = 0; cc < 4; cc++)
                *reinterpret_cast<float2*>(base + ((cc ^ j) << 1)) = make_float2(f0[cc], f1[cc]);
        }
        #pragma unroll
        for (int i = 0; i < 4; i++) {
            int u = tid + 256 * i;
            int n = u >> 2, j = u & 3;
            float* base = Bs + (((st * 4 + j) * BN + n) << 3);
            float f0[4] = {pb[i][0].x, pb[i][0].y, pb[i][0].z, pb[i][0].w};
            float f1[4] = {pb[i][1].x, pb[i][1].y, pb[i][1].z, pb[i][1].w};
            #pragma unroll
            for (int cc = 0; cc < 4; cc++)
                *reinterpret_cast<float2*>(base + ((cc ^ j) << 1)) = make_float2(f0[cc], f1[cc]);
        }
    };

    auto compute = [&](int st) {
        #pragma unroll
        for (int j = 0; j < 4; j++) {
            const int slot2 = ((c ^ j) << 1);
            const float* Aj = As + ((st * 4 + j) * TM << 3);
            const float* Bj = Bs + ((st * 4 + j) * BN << 3);
            float2 af[4][2];
            #pragma unroll
            for (int mt = 0; mt < 4; mt++) {
                int r0 = wm + mt * 16 + grp;
                af[mt][0] = *reinterpret_cast<const float2*>(Aj + (r0 << 3) + slot2);
                af[mt][1] = *reinterpret_cast<const float2*>(Aj + ((r0 + 8) << 3) + slot2);
            }
            uint32_t bf[8][2];
            #pragma unroll
            for (int nt = 0; nt < 8; nt++) {
                int n = wn + nt * 8 + grp;
                float2 bv = *reinterpret_cast<const float2*>(Bj + (n << 3) + slot2);
                bf[nt][0] = cvt_tf32_bits(bv.x);
                bf[nt][1] = cvt_tf32_bits(bv.y);
            }
            #pragma unroll
            for (int mt = 0; mt < 4; mt++) {
                uint32_t a0 = __float_as_uint(af[mt][0].x);
                uint32_t a1 = __float_as_uint(af[mt][1].x);
                uint32_t a2 = __float_as_uint(af[mt][0].y);
                uint32_t a3 = __float_as_uint(af[mt][1].y);
                #pragma unroll
                for (int nt = 0; nt < 8; nt++)
                    mma_tf32(acc[mt][nt][0], acc[mt][nt][1], acc[mt][nt][2], acc[mt][nt][3],
                             a0, a1, a2, a3, bf[nt][0], bf[nt][1]);
            }
        }
    };

    auto epilogue = [&](int e, int n0, const int* sr) {
        const float* bp = bias + (size_t)e * VOCAB + n0 + wn + c * 2;
        float2 bias2[8];
        #pragma unroll
        for (int nt = 0; nt < 8; nt++)
            bias2[nt] = *reinterpret_cast<const float2*>(bp + nt * 8);
        #pragma unroll
        for (int mt = 0; mt < 4; mt++) {
            const int r0 = wm + mt * 16 + grp;
            const int row0 = sr[r0];
            const int row1 = sr[r0 + 8];
            #pragma unroll
            for (int nt = 0; nt < 8; nt++) {
                const int col = n0 + wn + nt * 8 + c * 2;
                if (row0 >= 0) {
                    float2 o = make_float2(acc[mt][nt][0] + bias2[nt].x,
                                           acc[mt][nt][1] + bias2[nt].y);
                    *reinterpret_cast<float2*>(out + (size_t)row0 * VOCAB + col) = o;
                }
                if (row1 >= 0) {
                    float2 o = make_float2(acc[mt][nt][2] + bias2[nt].x,
                                           acc[mt][nt][3] + bias2[nt].y);
                    *reinterpret_cast<float2*>(out + (size_t)row1 * VOCAB + col) = o;
                }
            }
        }
    };

    // ---- bootstrap: grab first item ----
    if (tid == 0) s_nid[0] = atomicAdd(&g_work, 1);
    __syncthreads();
    {
        int id = s_nid[0];
        if (id >= n_items) return;    // uniform per CTA
        int ci = id % nchunks;
        cur_e = g_chunk_e[ci];
        cur_pm0 = g_chunk_pm0[ci];
        cur_n0 = (id / nchunks) * BN;
    }
    if (tid < TM) srow[tid] = g_prow[cur_pm0 + tid];   // srow[par=0]
    load_regs(cur_e, cur_pm0, cur_n0, 0);
    sts(0);
    if (tid == 0) s_nid[0] = atomicAdd(&g_work, 1);    // prefetch id for item 1
    __syncthreads();

    // ---- persistent mainloop ----
    for (;;) {
        for (int kt = 0; kt < NKI; kt++) {
            const int st = kt & 1;
            if (kt < NKI - 1) {
                load_regs(cur_e, cur_pm0, cur_n0, kt + 1);
            } else if (nxt_valid) {
                load_regs(nxt_e, nxt_pm0, nxt_n0, 0);   // next item's first loads
            }
            compute(st);
            if (kt < NKI - 1) {
                sts(1 - st);
                __syncthreads();
            }
            if (kt == 1) {
                // pick up prefetched id (visible via kt=0's sync), derive next item
                int nid = s_nid[0];
                nxt_valid = (nid < n_items);
                if (nxt_valid) {
                    int ci = nid % nchunks;
                    nxt_e = g_chunk_e[ci];
                    nxt_pm0 = g_chunk_pm0[ci];
                    nxt_n0 = (nid / nchunks) * BN;
                    if (tid < TM) srow[(par ^ 1) * TM + tid] = g_prow[nxt_pm0 + tid];
                }
            }
            if (kt == 2 && tid == 0) s_nid[0] = atomicAdd(&g_work, 1);  // prefetch id+2
        }

        // item done: epilogue overlaps the already-issued next-item LDGs
        epilogue(cur_e, cur_n0, srow + par * TM);
        #pragma unroll
        for (int mt = 0; mt < 4; mt++)
            #pragma unroll
            for (int nt = 0; nt < 8; nt++)
                #pragma unroll
                for (int q = 0; q < 4; q++) acc[mt][nt][q] = 0.f;

        if (!nxt_valid) break;
        sts(0);                 // fill stage 0 for next item (stage 0 idle since kt=30)
        __syncthreads();
        par ^= 1;
        cur_e = nxt_e; cur_pm0 = nxt_pm0; cur_n0 = nxt_n0;
    }
}

// ---------------------------------------------------------------------------
// Host launch
// ---------------------------------------------------------------------------
extern "C" void kernel_launch(void* const* d_in, const int* in_sizes, int n_in,
                              void* d_out, int out_size) {
    const float*    x    = (const float*)d_in[0];
    const uint32_t* ptr  = (const uint32_t*)d_in[1];
    const float*    W    = (const float*)d_in[2];
    const float*    bias = (const float*)d_in[3];
    float*          out  = (float*)d_out;

    static bool attr_done = false;
    if (!attr_done) {
        cudaFuncSetAttribute(tc_gemm_kernel,
                             cudaFuncAttributeMaxDynamicSharedMemorySize, SMEM_TOTAL);
        attr_done = true;
    }

    int nsm = 148;
    cudaDeviceGetAttribute(&nsm, cudaDevAttrMultiProcessorCount, 0);

    group_rows_kernel<<<1, 1024>>>(ptr);
    pack_kernel<<<XSROWS, 128>>>(x);
    tc_gemm_kernel<<<nsm, 256, SMEM_TOTAL>>>(W, bias, out);
}

// round 8
// speedup vs baseline: 1.2757x; 1.0823x over previous
#include <cuda_runtime.h>
#include <stdint.h>

#define NUM_EXPERTS 8
#define BATCH 4096
#define DM 1024
#define VOCAB 32000

#define TM 128                  // rows per chunk = BM
#define BN 256
#define BK 32
#define NKI (DM / BK)           // 32 k-iterations
#define MAXC 40                 // max chunks: 4096/128 + 8 pad
#define XSROWS (MAXC * TM)      // 5120 padded rows

// ---------------- device scratch (no allocations allowed) ----------------
__device__ int g_rows[BATCH];
__device__ int g_offsets[NUM_EXPERTS + 1];
__device__ int g_chunk_e[MAXC];
__device__ int g_chunk_pm0[MAXC];
__device__ int g_chunk_rows[MAXC];   // valid rows in this chunk (1..128)
__device__ int g_nchunks;
__device__ int g_prow[XSROWS];
__device__ float g_xs[(size_t)XSROWS * DM];  // tf32-rounded gathered x

// ---------------------------------------------------------------------------
// Kernel 1: group rows by expert (ptr % 8), build padded 128-row chunk table.
// Pointer dtype auto-detect (JAX x64-off downcasts int64->int32), as in R3.
// ---------------------------------------------------------------------------
__global__ void group_rows_kernel(const uint32_t* __restrict__ ptr_words) {
    __shared__ int counts[NUM_EXPERTS];
    __shared__ int cursor[NUM_EXPERTS];
    __shared__ int pad_off[NUM_EXPERTS];
    __shared__ int odd_nonzero;
    const int tid = threadIdx.x;

    if (tid == 0) odd_nonzero = 0;
    if (tid < NUM_EXPERTS) counts[tid] = 0;
    __syncthreads();

    int local_nz = 0;
    for (int i = tid; i < BATCH / 2; i += blockDim.x)
        if (ptr_words[2 * i + 1] != 0u) local_nz = 1;
    if (local_nz) atomicOr(&odd_nonzero, 1);
    __syncthreads();
    const bool is_i64 = (odd_nonzero == 0);

    for (int i = tid; i < BATCH; i += blockDim.x) {
        uint32_t v = is_i64 ? ptr_words[2 * i] : ptr_words[i];
        atomicAdd(&counts[v & (NUM_EXPERTS - 1)], 1);
    }
    __syncthreads();
    if (tid == 0) {
        int acc = 0, nc = 0, pbase = 0;
        for (int e = 0; e < NUM_EXPERTS; e++) {
            g_offsets[e] = acc;
            cursor[e] = acc;
            pad_off[e] = pbase;
            int cnt = counts[e];
            int nch = (cnt + TM - 1) / TM;
            for (int j = 0; j < nch; j++) {
                g_chunk_e[nc] = e;
                g_chunk_pm0[nc] = pbase + j * TM;
                int rem = cnt - j * TM;
                g_chunk_rows[nc] = rem > TM ? TM : rem;
                nc++;
            }
            pbase += nch * TM;
            acc += cnt;
        }
        g_offsets[NUM_EXPERTS] = acc;
        g_nchunks = nc;
    }
    __syncthreads();
    for (int i = tid; i < XSROWS; i += blockDim.x) g_prow[i] = -1;
    for (int i = tid; i < BATCH; i += blockDim.x) {
        uint32_t v = is_i64 ? ptr_words[2 * i] : ptr_words[i];
        int pos = atomicAdd(&cursor[v & (NUM_EXPERTS - 1)], 1);
        g_rows[pos] = i;
    }
    __syncthreads();
    for (int i = tid; i < BATCH; i += blockDim.x) {
        int e = 0;
        while (!(i >= g_offsets[e] && i < g_offsets[e + 1])) e++;
        g_prow[pad_off[e] + (i - g_offsets[e])] = g_rows[i];
    }
}

// ---------------------------------------------------------------------------
// Kernel 2: gather + RN-round x rows to tf32 into padded buffer (zeros pad).
// ---------------------------------------------------------------------------
__device__ __forceinline__ float to_tf32_rn(float v) {
    uint32_t b;
    asm("cvt.rna.tf32.f32 %0, %1;" : "=r"(b) : "f"(v));
    return __uint_as_float(b);
}
__device__ __forceinline__ uint32_t cvt_tf32_bits(float v) {
    uint32_t b;
    asm("cvt.rna.tf32.f32 %0, %1;" : "=r"(b) : "f"(v));
    return b;
}

__global__ void pack_kernel(const float* __restrict__ x) {
    const int p = blockIdx.x;
    const int r = g_prow[p];
    float4* dst = reinterpret_cast<float4*>(g_xs + (size_t)p * DM);
    if (r >= 0) {
        const float4* src = reinterpret_cast<const float4*>(x + (size_t)r * DM);
        for (int i = threadIdx.x; i < DM / 4; i += blockDim.x) {
            float4 v = src[i];
            v.x = to_tf32_rn(v.x); v.y = to_tf32_rn(v.y);
            v.z = to_tf32_rn(v.z); v.w = to_tf32_rn(v.w);
            dst[i] = v;
        }
    } else {
        float4 z = make_float4(0.f, 0.f, 0.f, 0.f);
        for (int i = threadIdx.x; i < DM / 4; i += blockDim.x) dst[i] = z;
    }
}

// ---------------------------------------------------------------------------
// Kernel 3: tf32 mma.sync GEMM (R5 structure) + zero-row MMA elimination.
// CTA = 128 rows x 256 vocab cols, 8 warps (2m x 4n), warp tile 64x64,
// BK=32 double-buffered smem with register staging. m-slices (16 rows) past
// the chunk's valid row count skip fragment loads + MMAs (warp-uniform guard).
// ---------------------------------------------------------------------------
__device__ __forceinline__ void mma_tf32(float& d0, float& d1, float& d2, float& d3,
                                         uint32_t a0, uint32_t a1, uint32_t a2, uint32_t a3,
                                         uint32_t b0, uint32_t b1) {
    asm volatile(
        "mma.sync.aligned.m16n8k8.row.col.f32.tf32.tf32.f32 "
        "{%0,%1,%2,%3}, {%4,%5,%6,%7}, {%8,%9}, {%0,%1,%2,%3};"
        : "+f"(d0), "+f"(d1), "+f"(d2), "+f"(d3)
        : "r"(a0), "r"(a1), "r"(a2), "r"(a3), "r"(b0), "r"(b1));
}

#define SMEM_TOTAL (512 + 2 * 4 * TM * 8 * 4 + 2 * 4 * BN * 8 * 4)  // 98816

__global__ void __launch_bounds__(256, 1)
tc_gemm_kernel(const float* __restrict__ W,
               const float* __restrict__ bias,
               float* __restrict__ out) {
    const int cx = blockIdx.x;
    if (cx >= g_nchunks) return;
    const int e = g_chunk_e[cx];
    const int pm0 = g_chunk_pm0[cx];
    const int rows = g_chunk_rows[cx];
    const int n0 = blockIdx.y * BN;

    extern __shared__ float sm[];
    int* srow = reinterpret_cast<int*>(sm);         // [128]
    float* As = sm + TM;                            // [2][4][TM][8]
    float* Bs = As + 2 * 4 * TM * 8;                // [2][4][BN][8]

    const int tid = threadIdx.x;
    const int w = tid >> 5, lane = tid & 31;
    const int wm = (w & 1) * 64, wn = (w >> 1) * 64;
    const int grp = lane >> 2, c = lane & 3;

    if (tid < TM) srow[tid] = g_prow[pm0 + tid];

    // number of live 16-row m-slices for this warp (0..4), warp-uniform
    int live = (rows - wm + 15) >> 4;
    if (live < 0) live = 0;
    if (live > 4) live = 4;

    const float* gW = W + (size_t)e * VOCAB * DM;

    float acc[4][8][4];
    #pragma unroll
    for (int mt = 0; mt < 4; mt++)
        #pragma unroll
        for (int nt = 0; nt < 8; nt++)
            #pragma unroll
            for (int q = 0; q < 4; q++) acc[mt][nt][q] = 0.f;

    float4 pa[2][2];     // A staging: 2 units x 32B
    float4 pb[4][2];     // B staging: 4 units x 32B

    auto load_regs = [&](int kt) {
        const int k0 = kt * BK;
        #pragma unroll
        for (int i = 0; i < 2; i++) {
            int u = tid + 256 * i;
            int m = u >> 2, j = u & 3;
            const float* ga = g_xs + (size_t)(pm0 + m) * DM + k0 + j * 8;
            pa[i][0] = *reinterpret_cast<const float4*>(ga);
            pa[i][1] = *reinterpret_cast<const float4*>(ga + 4);
        }
        #pragma unroll
        for (int i = 0; i < 4; i++) {
            int u = tid + 256 * i;
            int n = u >> 2, j = u & 3;
            const float* gb = gW + (size_t)(n0 + n) * DM + k0 + j * 8;
            pb[i][0] = *reinterpret_cast<const float4*>(gb);
            pb[i][1] = *reinterpret_cast<const float4*>(gb + 4);
        }
    };

    auto sts = [&](int st) {
        #pragma unroll
        for (int i = 0; i < 2; i++) {
            int u = tid + 256 * i;
            int m = u >> 2, j = u & 3;
            float* base = As + (((st * 4 + j) * TM + m) << 3);
            float f0[4] = {pa[i][0].x, pa[i][0].y, pa[i][0].z, pa[i][0].w};
            float f1[4] = {pa[i][1].x, pa[i][1].y, pa[i][1].z, pa[i][1].w};
            #pragma unroll
            for (int cc = 0; cc < 4; cc++)
                *reinterpret_cast<float2*>(base + ((cc ^ j) << 1)) = make_float2(f0[cc], f1[cc]);
        }
        #pragma unroll
        for (int i = 0; i < 4; i++) {
            int u = tid + 256 * i;
            int n = u >> 2, j = u & 3;
            float* base = Bs + (((st * 4 + j) * BN + n) << 3);
            float f0[4] = {pb[i][0].x, pb[i][0].y, pb[i][0].z, pb[i][0].w};
            float f1[4] = {pb[i][1].x, pb[i][1].y, pb[i][1].z, pb[i][1].w};
            #pragma unroll
            for (int cc = 0; cc < 4; cc++)
                *reinterpret_cast<float2*>(base + ((cc ^ j) << 1)) = make_float2(f0[cc], f1[cc]);
        }
    };

    auto compute = [&](int st) {
        if (live == 0) return;                 // warp-uniform: whole warp idle
        #pragma unroll
        for (int j = 0; j < 4; j++) {
            const int slot2 = ((c ^ j) << 1);
            const float* Aj = As + ((st * 4 + j) * TM << 3);
            const float* Bj = Bs + ((st * 4 + j) * BN << 3);
            uint32_t bf[8][2];
            #pragma unroll
            for (int nt = 0; nt < 8; nt++) {
                int n = wn + nt * 8 + grp;
                float2 bv = *reinterpret_cast<const float2*>(Bj + (n << 3) + slot2);
                bf[nt][0] = cvt_tf32_bits(bv.x);
                bf[nt][1] = cvt_tf32_bits(bv.y);
            }
            #pragma unroll
            for (int mt = 0; mt < 4; mt++) {
                if (mt >= live) break;         // warp-uniform guard: skip dead slices
                int r0 = wm + mt * 16 + grp;
                float2 a0v = *reinterpret_cast<const float2*>(Aj + (r0 << 3) + slot2);
                float2 a1v = *reinterpret_cast<const float2*>(Aj + ((r0 + 8) << 3) + slot2);
                uint32_t a0 = __float_as_uint(a0v.x);
                uint32_t a1 = __float_as_uint(a1v.x);
                uint32_t a2 = __float_as_uint(a0v.y);
                uint32_t a3 = __float_as_uint(a1v.y);
                #pragma unroll
                for (int nt = 0; nt < 8; nt++)
                    mma_tf32(acc[mt][nt][0], acc[mt][nt][1], acc[mt][nt][2], acc[mt][nt][3],
                             a0, a1, a2, a3, bf[nt][0], bf[nt][1]);
            }
        }
    };

    load_regs(0);
    sts(0);
    __syncthreads();

    for (int kt = 0; kt < NKI; kt++) {
        const int st = kt & 1;
        if (kt + 1 < NKI) load_regs(kt + 1);
        compute(st);
        if (kt + 1 < NKI) {
            sts(1 - st);
            __syncthreads();
        }
    }

    // ---- epilogue: bias + scatter float2 stores ----
    if (live > 0) {
        const float* bp = bias + (size_t)e * VOCAB + n0 + wn + c * 2;
        float2 bias2[8];
        #pragma unroll
        for (int nt = 0; nt < 8; nt++)
            bias2[nt] = *reinterpret_cast<const float2*>(bp + nt * 8);

        #pragma unroll
        for (int mt = 0; mt < 4; mt++) {
            if (mt >= live) break;
            const int r0 = wm + mt * 16 + grp;
            const int row0 = srow[r0];
            const int row1 = srow[r0 + 8];
            #pragma unroll
            for (int nt = 0; nt < 8; nt++) {
                const int col = n0 + wn + nt * 8 + c * 2;
                if (row0 >= 0) {
                    float2 o = make_float2(acc[mt][nt][0] + bias2[nt].x,
                                           acc[mt][nt][1] + bias2[nt].y);
                    *reinterpret_cast<float2*>(out + (size_t)row0 * VOCAB + col) = o;
                }
                if (row1 >= 0) {
                    float2 o = make_float2(acc[mt][nt][2] + bias2[nt].x,
                                           acc[mt][nt][3] + bias2[nt].y);
                    *reinterpret_cast<float2*>(out + (size_t)row1 * VOCAB + col) = o;
                }
            }
        }
    }
}

// ---------------------------------------------------------------------------
// Host launch
// ---------------------------------------------------------------------------
extern "C" void kernel_launch(void* const* d_in, const int* in_sizes, int n_in,
                              void* d_out, int out_size) {
    const float*    x    = (const float*)d_in[0];
    const uint32_t* ptr  = (const uint32_t*)d_in[1];
    const float*    W    = (const float*)d_in[2];
    const float*    bias = (const float*)d_in[3];
    float*          out  = (float*)d_out;

    static bool attr_done = false;
    if (!attr_done) {
        cudaFuncSetAttribute(tc_gemm_kernel,
                             cudaFuncAttributeMaxDynamicSharedMemorySize, SMEM_TOTAL);
        attr_done = true;
    }

    group_rows_kernel<<<1, 1024>>>(ptr);
    pack_kernel<<<XSROWS, 128>>>(x);

    dim3 grid(MAXC, VOCAB / BN);   // chunk-fastest -> L2 absorbs W reuse
    tc_gemm_kernel<<<grid, 256, SMEM_TOTAL>>>(W, bias, out);
}